// round 16
// baseline (speedup 1.0000x reference)
#include <cuda_runtime.h>
#include <cstdint>

#define NH     16
#define DH     64
#define LSEQ   1024
#define NB     4
#define DMODEL 1024
#define NPOS   257
#define TP     288           // padded stride for T (9 k-chunks of 32)
#define BH     (NB*NH)       // 64
#define ROWS   (BH*LSEQ)     // 65536
#define MROW   (NB*LSEQ)     // 4096

// ---------------- scratch (device globals; no allocation allowed) ----------
__device__ float  g_Q[(size_t)ROWS*DH];       // [B,H,L,d]
__device__ float  g_K[(size_t)ROWS*DH];
__device__ float  g_V[(size_t)ROWS*DH];
__device__ float  g_R[(size_t)ROWS*NPOS];     // Q . posK^T
__device__ float  g_T[(size_t)ROWS*TP];       // scattered probs (padded stride)
__device__ float  g_S[(size_t)ROWS*LSEQ];     // RAW scores (268MB)
__device__ float2 g_stat[(size_t)ROWS*8];     // per (row, ktile): (max, sumexp)
__device__ float2 g_stat2[(size_t)ROWS];      // per row: (max, 1/l)
__device__ float  g_O[(size_t)MROW*DMODEL];   // (O1+O2) in [B,L,D] layout

// ---------------- tf32 mma helpers -----------------------------------------
__device__ __forceinline__ unsigned f2tf(float f) {
    unsigned u;
    asm("cvt.rna.tf32.f32 %0, %1;" : "=r"(u) : "f"(f));
    return u;
}

__device__ __forceinline__ void mma_tf32(float* d, const unsigned* a, const unsigned* b) {
    asm volatile(
        "mma.sync.aligned.m16n8k8.row.col.f32.tf32.tf32.f32 "
        "{%0,%1,%2,%3}, {%4,%5,%6,%7}, {%8,%9}, {%0,%1,%2,%3};\n"
        : "+f"(d[0]), "+f"(d[1]), "+f"(d[2]), "+f"(d[3])
        : "r"(a[0]), "r"(a[1]), "r"(a[2]), "r"(a[3]), "r"(b[0]), "r"(b[1]));
}

__device__ __forceinline__ void ldsm_x4(unsigned* r, uint32_t addr) {
    asm volatile("ldmatrix.sync.aligned.m8n8.x4.shared.b16 {%0,%1,%2,%3}, [%4];"
        : "=r"(r[0]), "=r"(r[1]), "=r"(r[2]), "=r"(r[3]) : "r"(addr));
}

// ======= big GEMM core (R10-proven: single buffer, prefetch, ldmatrix) ======
template<bool HEADMAJOR>
__device__ __forceinline__ void gemm_core(
    const float* __restrict__ A, const float* __restrict__ W,
    const float* __restrict__ bias, float* __restrict__ C)
{
    const int K = DMODEL, N = DMODEL;
    __shared__ __align__(16) unsigned As[128][36];
    __shared__ __align__(16) unsigned Bs[32][136];
    int tid = threadIdx.x;
    int bm = blockIdx.y * 128, bn = blockIdx.x * 128;
    int warp = tid >> 5, lane = tid & 31;
    int wm = (warp >> 2) * 64, wn = (warp & 3) * 32;
    int g = lane >> 2, i4 = lane & 3;

    int lrow = (lane & 7) + 8 * ((lane >> 3) & 1);
    int lcol = 4 * (lane >> 4);
    uint32_t a_base = (uint32_t)__cvta_generic_to_shared(&As[0][0]);

    float acc[4][4][4] = {};
    int am = tid >> 3, ak = (tid & 7) * 4;
    int bk2 = tid >> 5, bn4 = (tid & 31) * 4;

    float4 ra[4], rw[4];
#pragma unroll
    for (int r = 0; r < 4; r++) {
        ra[r] = *(const float4*)&A[(size_t)(bm + am + 32 * r) * K + ak];
        rw[r] = *(const float4*)&W[(size_t)(bk2 + 8 * r) * N + bn + bn4];
    }

    for (int k0 = 0; k0 < K; k0 += 32) {
#pragma unroll
        for (int r = 0; r < 4; r++) {
            *(uint4*)&As[am + 32 * r][ak] =
                make_uint4(f2tf(ra[r].x), f2tf(ra[r].y), f2tf(ra[r].z), f2tf(ra[r].w));
            *(uint4*)&Bs[bk2 + 8 * r][bn4] =
                make_uint4(f2tf(rw[r].x), f2tf(rw[r].y), f2tf(rw[r].z), f2tf(rw[r].w));
        }
        __syncthreads();
        if (k0 + 32 < K) {
#pragma unroll
            for (int r = 0; r < 4; r++) {
                ra[r] = *(const float4*)&A[(size_t)(bm + am + 32 * r) * K + k0 + 32 + ak];
                rw[r] = *(const float4*)&W[(size_t)(k0 + 32 + bk2 + 8 * r) * N + bn + bn4];
            }
        }
#pragma unroll
        for (int ks = 0; ks < 32; ks += 8) {
            unsigned af[4][4], bf[4][2];
#pragma unroll
            for (int mi = 0; mi < 4; mi++)
                ldsm_x4(af[mi],
                    a_base + ((wm + 16 * mi + lrow) * 36 + ks + lcol) * 4);
#pragma unroll
            for (int ni = 0; ni < 4; ni++) {
                bf[ni][0] = Bs[ks + i4][wn + 8 * ni + g];
                bf[ni][1] = Bs[ks + i4 + 4][wn + 8 * ni + g];
            }
#pragma unroll
            for (int mi = 0; mi < 4; mi++)
#pragma unroll
                for (int ni = 0; ni < 4; ni++)
                    mma_tf32(acc[mi][ni], af[mi], bf[ni]);
        }
        __syncthreads();
    }

#pragma unroll
    for (int mi = 0; mi < 4; mi++) {
#pragma unroll
        for (int ni = 0; ni < 4; ni++) {
#pragma unroll
            for (int e = 0; e < 4; e++) {
                int r = bm + wm + 16 * mi + g + (e >> 1) * 8;
                int c = bn + wn + 8 * ni + 2 * i4 + (e & 1);
                float v = acc[mi][ni][e] + bias[c];
                if (HEADMAJOR) {
                    int b = r >> 10, l = r & 1023, h = c >> 6, dd = c & 63;
                    C[(((size_t)(b * NH + h) * LSEQ + l) << 6) + dd] = v;
                } else {
                    C[(size_t)r * DMODEL + c] = v;
                }
            }
        }
    }
}

// ========== merged QKV projection (z selects Q/K/V), head-major =============
__global__ void __launch_bounds__(256) gemm_qkv(
    const float* __restrict__ A,
    const float* __restrict__ Wq, const float* __restrict__ bq,
    const float* __restrict__ Wk, const float* __restrict__ bk,
    const float* __restrict__ Wv, const float* __restrict__ bv)
{
    int zz = blockIdx.z;
    const float* W    = (zz == 0) ? Wq : (zz == 1) ? Wk : Wv;
    const float* bias = (zz == 0) ? bq : (zz == 1) ? bk : bv;
    float* C          = (zz == 0) ? g_Q : (zz == 1) ? g_K : g_V;
    gemm_core<true>(A, W, bias, C);
}

// ============ out projection: out = g_O @ Wo + bo (row-major) ===============
__global__ void __launch_bounds__(256) gemm_out(
    const float* __restrict__ W, const float* __restrict__ bias,
    float* __restrict__ C)
{
    gemm_core<false>(g_O, W, bias, C);
}

// ======== R = Q @ posK^T (tf32 mma; M=65536, N=257->3x128, K=64) ===========
__global__ void __launch_bounds__(256) gemm_qposk_t(const float* __restrict__ posK)
{
    __shared__ __align__(16) unsigned As[128][36];
    __shared__ __align__(16) unsigned Bs[32][132];
    int tid = threadIdx.x;
    int bm = blockIdx.y * 128, bn = blockIdx.x * 128;
    int warp = tid >> 5, lane = tid & 31;
    int wm = (warp >> 2) * 64, wn = (warp & 3) * 32;
    int g = lane >> 2, i4 = lane & 3;

    int lrow = (lane & 7) + 8 * ((lane >> 3) & 1);
    int lcol = 4 * (lane >> 4);
    uint32_t a_base = (uint32_t)__cvta_generic_to_shared(&As[0][0]);

    float acc[4][4][4] = {};
    int am = tid >> 3, ak = (tid & 7) * 4;
    int nl = tid >> 3, k4 = (tid & 7) * 4;

    for (int k0 = 0; k0 < DH; k0 += 32) {
#pragma unroll
        for (int r = 0; r < 4; r++) {
            float4 v = *(const float4*)&g_Q[(size_t)(bm + am + 32 * r) * DH + k0 + ak];
            *(uint4*)&As[am + 32 * r][ak] =
                make_uint4(f2tf(v.x), f2tf(v.y), f2tf(v.z), f2tf(v.w));
            int n = bn + nl + 32 * r;
            float4 w = make_float4(0.f, 0.f, 0.f, 0.f);
            if (n < NPOS) w = *(const float4*)&posK[(size_t)n * DH + k0 + k4];
            Bs[k4 + 0][nl + 32 * r] = f2tf(w.x);
            Bs[k4 + 1][nl + 32 * r] = f2tf(w.y);
            Bs[k4 + 2][nl + 32 * r] = f2tf(w.z);
            Bs[k4 + 3][nl + 32 * r] = f2tf(w.w);
        }
        __syncthreads();
#pragma unroll
        for (int ks = 0; ks < 32; ks += 8) {
            unsigned af[4][4], bf[4][2];
#pragma unroll
            for (int mi = 0; mi < 4; mi++)
                ldsm_x4(af[mi],
                    a_base + ((wm + 16 * mi + lrow) * 36 + ks + lcol) * 4);
#pragma unroll
            for (int ni = 0; ni < 4; ni++) {
                bf[ni][0] = Bs[ks + i4][wn + 8 * ni + g];
                bf[ni][1] = Bs[ks + i4 + 4][wn + 8 * ni + g];
            }
#pragma unroll
            for (int mi = 0; mi < 4; mi++)
#pragma unroll
                for (int ni = 0; ni < 4; ni++)
                    mma_tf32(acc[mi][ni], af[mi], bf[ni]);
        }
        __syncthreads();
    }

#pragma unroll
    for (int mi = 0; mi < 4; mi++) {
#pragma unroll
        for (int ni = 0; ni < 4; ni++) {
#pragma unroll
            for (int e = 0; e < 4; e++) {
                int r = bm + wm + 16 * mi + g + (e >> 1) * 8;
                int n = bn + wn + 8 * ni + 2 * i4 + (e & 1);
                if (n < NPOS) g_R[(size_t)r * NPOS + n] = acc[mi][ni][e];
            }
        }
    }
}

// ===== S = (Q K^T + gather(R)) * 0.125 * pad  +  per-tile softmax stats =====
// Off-diag tiles: one r2 per row. float2 stores. Shuffle-reduced stats.
__global__ void __launch_bounds__(256) attn_scores_t(const float* __restrict__ pad)
{
    __shared__ __align__(16) unsigned Qs[128][36];
    __shared__ __align__(16) unsigned Ks[128][36];
    int z = blockIdx.z;
    const float* Qp = g_Q + (size_t)z * LSEQ * DH;
    const float* Kp = g_K + (size_t)z * LSEQ * DH;
    int bm = blockIdx.y * 128, bn = blockIdx.x * 128;
    int tid = threadIdx.x;
    int warp = tid >> 5, lane = tid & 31;
    int wm = (warp >> 2) * 64, wn = (warp & 3) * 32;
    int g = lane >> 2, i4 = lane & 3;

    int lrow = (lane & 7) + 8 * ((lane >> 3) & 1);
    int lcol = 4 * (lane >> 4);
    int brow = (lane & 7) + 8 * (lane >> 4);
    int bcol = 4 * ((lane >> 3) & 1);
    uint32_t q_base = (uint32_t)__cvta_generic_to_shared(&Qs[0][0]);
    uint32_t k_base = (uint32_t)__cvta_generic_to_shared(&Ks[0][0]);

    float acc[4][4][4] = {};
    int am = tid >> 3, ak = (tid & 7) * 4;

    for (int k0 = 0; k0 < DH; k0 += 32) {
#pragma unroll
        for (int r = 0; r < 4; r++) {
            float4 v = *(const float4*)&Qp[(size_t)(bm + am + 32 * r) * DH + k0 + ak];
            *(uint4*)&Qs[am + 32 * r][ak] =
                make_uint4(f2tf(v.x), f2tf(v.y), f2tf(v.z), f2tf(v.w));
            float4 w = *(const float4*)&Kp[(size_t)(bn + am + 32 * r) * DH + k0 + ak];
            *(uint4*)&Ks[am + 32 * r][ak] =
                make_uint4(f2tf(w.x), f2tf(w.y), f2tf(w.z), f2tf(w.w));
        }
        __syncthreads();
#pragma unroll
        for (int ks = 0; ks < 32; ks += 8) {
            unsigned af[4][4], bfr[2][4];
#pragma unroll
            for (int mi = 0; mi < 4; mi++)
                ldsm_x4(af[mi],
                    q_base + ((wm + 16 * mi + lrow) * 36 + ks + lcol) * 4);
#pragma unroll
            for (int p = 0; p < 2; p++)
                ldsm_x4(bfr[p],
                    k_base + ((wn + 16 * p + brow) * 36 + ks + bcol) * 4);
#pragma unroll
            for (int mi = 0; mi < 4; mi++)
#pragma unroll
                for (int ni = 0; ni < 4; ni++)
                    mma_tf32(acc[mi][ni], af[mi], &bfr[ni >> 1][(ni & 1) * 2]);
        }
        __syncthreads();
    }

    int b = z >> 4;
    int warp4 = warp & 3;
    float* smax = (float*)&Qs[0][0];   // 128*4
    float* ssum = smax + 512;          // 128*4
    float* rowm = ssum + 512;          // 128
    float* padS = (float*)&Ks[0][0];   // 128
    float* rowr = padS + 128;          // 128

    bool diag = (bn - bm < 256) && (bm - bn < 256);
    if (tid < 128) {
        padS[tid] = pad[b * LSEQ + bn + tid];
        if (!diag) {
            int q = bm + tid;
            rowr[tid] = g_R[((size_t)z * LSEQ + q) * NPOS + ((bn > bm) ? 256 : 0)];
        }
    }
    __syncthreads();

    // pass 1: paired score computation + float2 store; shuffle-reduced max
#pragma unroll
    for (int mi = 0; mi < 4; mi++) {
#pragma unroll
        for (int e1 = 0; e1 < 2; e1++) {
            int rl = wm + 16 * mi + g + 8 * e1;
            int q = bm + rl;
            float mx = -3.0e38f;
            float r2c = diag ? 0.f : rowr[rl];
            const float* Rrow = &g_R[((size_t)z * LSEQ + q) * NPOS + 128];
            float* Srow = &g_S[((size_t)z * LSEQ + q) * LSEQ];
#pragma unroll
            for (int ni = 0; ni < 4; ni++) {
                int kp0 = bn + wn + 8 * ni + 2 * i4;
                float r20 = r2c, r21 = r2c;
                if (diag) {
                    int d0 = min(max(kp0 - q, -128), 128);
                    int d1 = min(max(kp0 + 1 - q, -128), 128);
                    r20 = Rrow[d0];
                    r21 = Rrow[d1];
                }
                float2 pd = *(float2*)&padS[kp0 - bn];
                float s0 = (acc[mi][ni][e1 * 2]     + r20) * 0.125f * pd.x;
                float s1 = (acc[mi][ni][e1 * 2 + 1] + r21) * 0.125f * pd.y;
                *(float2*)&Srow[kp0] = make_float2(s0, s1);
                acc[mi][ni][e1 * 2]     = s0;
                acc[mi][ni][e1 * 2 + 1] = s1;
                mx = fmaxf(mx, fmaxf(s0, s1));
            }
            mx = fmaxf(mx, __shfl_xor_sync(0xffffffffu, mx, 1));
            mx = fmaxf(mx, __shfl_xor_sync(0xffffffffu, mx, 2));
            if (i4 == 0) smax[rl * 4 + warp4] = mx;
        }
    }
    __syncthreads();
    if (tid < 128) {
        float m = smax[tid * 4];
#pragma unroll
        for (int j = 1; j < 4; j++) m = fmaxf(m, smax[tid * 4 + j]);
        rowm[tid] = m;
    }
    __syncthreads();
#pragma unroll
    for (int mi = 0; mi < 4; mi++) {
#pragma unroll
        for (int e1 = 0; e1 < 2; e1++) {
            int rl = wm + 16 * mi + g + 8 * e1;
            float m = rowm[rl];
            float se = 0.f;
#pragma unroll
            for (int ni = 0; ni < 4; ni++)
#pragma unroll
                for (int e0 = 0; e0 < 2; e0++)
                    se += __expf(acc[mi][ni][e1 * 2 + e0] - m);
            se += __shfl_xor_sync(0xffffffffu, se, 1);
            se += __shfl_xor_sync(0xffffffffu, se, 2);
            if (i4 == 0) ssum[rl * 4 + warp4] = se;
        }
    }
    __syncthreads();
    if (tid < 128) {
        float l = 0.f;
#pragma unroll
        for (int j = 0; j < 4; j++) l += ssum[tid * 4 + j];
        int q = bm + tid;
        g_stat[((size_t)z * LSEQ + q) * 8 + blockIdx.x] = make_float2(rowm[tid], l);
    }
}

// ====== combine per-tile stats -> per-row (max, 1/l) ========================
__global__ void __launch_bounds__(256) combine_stats()
{
    int row = blockIdx.x * 256 + threadIdx.x;
    const float2* st = &g_stat[(size_t)row * 8];
    float m = st[0].x;
#pragma unroll
    for (int j = 1; j < 8; j++) m = fmaxf(m, st[j].x);
    float l = 0.f;
#pragma unroll
    for (int j = 0; j < 8; j++) l += st[j].y * __expf(st[j].x - m);
    g_stat2[row] = make_float2(m, 1.f / l);
}

// ====== O1 = P @ V fused with T scatter (P on the fly from raw S) ===========
// Also zeroes this row-block's uncovered T bins (no zero_T kernel needed).
__global__ void __launch_bounds__(256) gemm_av_t()
{
    __shared__ __align__(16) unsigned As[128][36];
    __shared__ __align__(16) unsigned Bs[32][72];
    __shared__ float rs[256];
    int z = blockIdx.y;
    const float* S = g_S + (size_t)z * LSEQ * LSEQ;
    const float* V = g_V + (size_t)z * LSEQ * DH;
    int bm = blockIdx.x * 128;
    int tid = threadIdx.x;
    int warp = tid >> 5, lane = tid & 31;
    int wm = (warp >> 1) * 32, wn = (warp & 1) * 32;
    int g = lane >> 2, i4 = lane & 3;

    int lrow = (lane & 7) + 8 * ((lane >> 3) & 1);
    int lcol = 4 * (lane >> 4);
    uint32_t a_base = (uint32_t)__cvta_generic_to_shared(&As[0][0]);

    if (tid < 128) {
        int q = bm + tid;
        float2 st = g_stat2[(size_t)z * LSEQ + q];
        rs[tid * 2] = st.x;
        rs[tid * 2 + 1] = st.y;
        // zero padding tail + uncovered middle bins for this row
        float* Trow = g_T + (size_t)((size_t)z * LSEQ + q) * TP;
        for (int p = NPOS; p < TP; p++) Trow[p] = 0.f;
        for (int p = 1; p <= 127 - q; p++) Trow[p] = 0.f;        // k = q+p-128 < 0
        for (int p = 1152 - q; p <= 255; p++) Trow[p] = 0.f;     // k > 1023
    }
    __syncthreads();

    float acc[2][4][4] = {};
    int am = tid >> 3, ak = (tid & 7) * 4;
    int vk = tid >> 4, vn4 = (tid & 15) * 4;
    float te0[4] = {}, te1[4] = {};

    float4 ra[4], rv[2];
#pragma unroll
    for (int r = 0; r < 4; r++)
        ra[r] = *(const float4*)&S[(size_t)(bm + am + 32 * r) * LSEQ + ak];
#pragma unroll
    for (int r = 0; r < 2; r++)
        rv[r] = *(const float4*)&V[(size_t)(vk + 16 * r) * DH + vn4];

    for (int k0 = 0; k0 < LSEQ; k0 += 32) {
#pragma unroll
        for (int r = 0; r < 4; r++) {
            int rl = am + 32 * r;
            float m = rs[2 * rl], il = rs[2 * rl + 1];
            float p0 = __expf(ra[r].x - m) * il;
            float p1 = __expf(ra[r].y - m) * il;
            float p2 = __expf(ra[r].z - m) * il;
            float p3 = __expf(ra[r].w - m) * il;
            *(uint4*)&As[rl][ak] = make_uint4(f2tf(p0), f2tf(p1), f2tf(p2), f2tf(p3));
            float* Trow = g_T + (size_t)((size_t)z * LSEQ + bm + rl) * TP;
            int binb = k0 + ak - bm - rl + 128;
            if (binb >= 1 && binb <= 252) {    // whole group in middle bins
                Trow[binb]     = p0;
                Trow[binb + 1] = p1;
                Trow[binb + 2] = p2;
                Trow[binb + 3] = p3;
            } else {
                if (binb     <= 0) te0[r] += p0; else if (binb     >= 256) te1[r] += p0; else Trow[binb]     = p0;
                if (binb + 1 <= 0) te0[r] += p1; else if (binb + 1 >= 256) te1[r] += p1; else Trow[binb + 1] = p1;
                if (binb + 2 <= 0) te0[r] += p2; else if (binb + 2 >= 256) te1[r] += p2; else Trow[binb + 2] = p2;
                if (binb + 3 <= 0) te0[r] += p3; else if (binb + 3 >= 256) te1[r] += p3; else Trow[binb + 3] = p3;
            }
        }
#pragma unroll
        for (int r = 0; r < 2; r++)
            *(uint4*)&Bs[vk + 16 * r][vn4] =
                make_uint4(f2tf(rv[r].x), f2tf(rv[r].y), f2tf(rv[r].z), f2tf(rv[r].w));
        __syncthreads();
        if (k0 + 32 < LSEQ) {
#pragma unroll
            for (int r = 0; r < 4; r++)
                ra[r] = *(const float4*)&S[(size_t)(bm + am + 32 * r) * LSEQ + k0 + 32 + ak];
#pragma unroll
            for (int r = 0; r < 2; r++)
                rv[r] = *(const float4*)&V[(size_t)(k0 + 32 + vk + 16 * r) * DH + vn4];
        }
#pragma unroll
        for (int ks = 0; ks < 32; ks += 8) {
            unsigned af[2][4], bf[4][2];
#pragma unroll
            for (int mi = 0; mi < 2; mi++)
                ldsm_x4(af[mi],
                    a_base + ((wm + 16 * mi + lrow) * 36 + ks + lcol) * 4);
#pragma unroll
            for (int ni = 0; ni < 4; ni++) {
                bf[ni][0] = Bs[ks + i4][wn + 8 * ni + g];
                bf[ni][1] = Bs[ks + i4 + 4][wn + 8 * ni + g];
            }
#pragma unroll
            for (int mi = 0; mi < 2; mi++)
#pragma unroll
                for (int ni = 0; ni < 4; ni++)
                    mma_tf32(acc[mi][ni], af[mi], bf[ni]);
        }
        __syncthreads();
    }

    {
        float* e0s = (float*)&As[0][0];
        float* e1s = e0s + 1024;
#pragma unroll
        for (int r = 0; r < 4; r++) {
            e0s[(am + 32 * r) * 8 + (tid & 7)] = te0[r];
            e1s[(am + 32 * r) * 8 + (tid & 7)] = te1[r];
        }
        __syncthreads();
        if (tid < 128) {
            float a0 = 0.f, a1 = 0.f;
#pragma unroll
            for (int j = 0; j < 8; j++) { a0 += e0s[tid * 8 + j]; a1 += e1s[tid * 8 + j]; }
            float* Trow = g_T + (size_t)((size_t)z * LSEQ + bm + tid) * TP;
            Trow[0] = a0;
            Trow[256] = a1;
        }
    }

    int b = z >> 4, h = z & 15;
#pragma unroll
    for (int mi = 0; mi < 2; mi++) {
#pragma unroll
        for (int ni = 0; ni < 4; ni++) {
#pragma unroll
            for (int e = 0; e < 4; e++) {
                int q = bm + wm + 16 * mi + g + (e >> 1) * 8;
                int n = wn + 8 * ni + 2 * i4 + (e & 1);
                g_O[((size_t)(b * LSEQ + q)) * DMODEL + h * 64 + n] = acc[mi][ni][e];
            }
        }
    }
}

// ====== g_O += T @ posV (tf32 mma; M=65536, N=64, K=288 padded) ============
__global__ void __launch_bounds__(256) gemm_tposv_t(const float* __restrict__ posV)
{
    __shared__ __align__(16) unsigned As[128][36];
    __shared__ __align__(16) unsigned Bs[32][72];
    int bm = blockIdx.x * 128;
    int tid = threadIdx.x;
    int warp = tid >> 5, lane = tid & 31;
    int wm = warp * 16;
    int g = lane >> 2, i4 = lane & 3;

    int lrow = (lane & 7) + 8 * ((lane >> 3) & 1);
    int lcol = 4 * (lane >> 4);
    uint32_t a_base = (uint32_t)__cvta_generic_to_shared(&As[0][0]);

    float acc[8][4] = {};
    int am = tid >> 3, ak = (tid & 7) * 4;
    int vk = tid >> 4, vn4 = (tid & 15) * 4;

    for (int k0 = 0; k0 < TP; k0 += 32) {
#pragma unroll
        for (int r = 0; r < 4; r++) {
            float4 v = *(const float4*)&g_T[(size_t)(bm + am + 32 * r) * TP + k0 + ak];
            *(uint4*)&As[am + 32 * r][ak] =
                make_uint4(f2tf(v.x), f2tf(v.y), f2tf(v.z), f2tf(v.w));
        }
#pragma unroll
        for (int r = 0; r < 2; r++) {
            int k = k0 + vk + 16 * r;
            float4 w = make_float4(0.f, 0.f, 0.f, 0.f);
            if (k < NPOS) w = *(const float4*)&posV[(size_t)k * DH + vn4];
            *(uint4*)&Bs[vk + 16 * r][vn4] =
                make_uint4(f2tf(w.x), f2tf(w.y), f2tf(w.z), f2tf(w.w));
        }
        __syncthreads();
#pragma unroll
        for (int ks = 0; ks < 32; ks += 8) {
            unsigned af[4], bf[8][2];
            ldsm_x4(af, a_base + ((wm + lrow) * 36 + ks + lcol) * 4);
#pragma unroll
            for (int ni = 0; ni < 8; ni++) {
                bf[ni][0] = Bs[ks + i4][8 * ni + g];
                bf[ni][1] = Bs[ks + i4 + 4][8 * ni + g];
            }
#pragma unroll
            for (int ni = 0; ni < 8; ni++)
                mma_tf32(acc[ni], af, bf[ni]);
        }
        __syncthreads();
    }

#pragma unroll
    for (int ni = 0; ni < 8; ni++) {
#pragma unroll
        for (int e = 0; e < 4; e++) {
            int r = bm + wm + g + (e >> 1) * 8;
            int z = r >> 10, q = r & 1023;
            int b = z >> 4, h = z & 15;
            int n = 8 * ni + 2 * i4 + (e & 1);
            size_t idx = ((size_t)(b * LSEQ + q)) * DMODEL + h * 64 + n;
            g_O[idx] += acc[ni][e];
        }
    }
}

// ---------------------------------------------------------------------------
extern "C" void kernel_launch(void* const* d_in, const int* in_sizes, int n_in,
                              void* d_out, int out_size)
{
    const float* x    = (const float*)d_in[0];
    const float* pad  = (const float*)d_in[1];
    const float* Wq   = (const float*)d_in[2];
    const float* bq   = (const float*)d_in[3];
    const float* Wk   = (const float*)d_in[4];
    const float* bk   = (const float*)d_in[5];
    const float* Wv   = (const float*)d_in[6];
    const float* bv   = (const float*)d_in[7];
    const float* Wo   = (const float*)d_in[8];
    const float* bo   = (const float*)d_in[9];
    const float* posK = (const float*)d_in[10];
    const float* posV = (const float*)d_in[11];
    float* out = (float*)d_out;

    gemm_qkv<<<dim3(DMODEL / 128, MROW / 128, 3), 256>>>(x, Wq, bq, Wk, bk, Wv, bv);
    gemm_qposk_t<<<dim3(3, ROWS / 128), 256>>>(posK);
    attn_scores_t<<<dim3(8, 8, BH), 256>>>(pad);
    combine_stats<<<ROWS / 256, 256>>>();
    gemm_av_t<<<dim3(8, BH), 256>>>();
    gemm_tposv_t<<<dim3(ROWS / 128), 256>>>(posV);
    gemm_out<<<dim3(DMODEL / 128, MROW / 128), 256>>>(Wo, bo, out);
}

// round 17
// speedup vs baseline: 1.0208x; 1.0208x over previous
#include <cuda_runtime.h>
#include <cstdint>

#define NH     16
#define DH     64
#define LSEQ   1024
#define NB     4
#define DMODEL 1024
#define NPOS   257
#define TP     288           // padded stride for T (9 k-chunks of 32)
#define BH     (NB*NH)       // 64
#define ROWS   (BH*LSEQ)     // 65536
#define MROW   (NB*LSEQ)     // 4096

// ---------------- scratch (device globals; no allocation allowed) ----------
__device__ float  g_Q[(size_t)ROWS*DH];       // [B,H,L,d]
__device__ float  g_K[(size_t)ROWS*DH];
__device__ float  g_V[(size_t)ROWS*DH];
__device__ float  g_R[(size_t)ROWS*NPOS];     // Q . posK^T
__device__ float  g_T[(size_t)ROWS*TP];       // scattered probs (padded stride)
__device__ float  g_S[(size_t)ROWS*LSEQ];     // RAW scores (268MB)
__device__ float2 g_stat[(size_t)ROWS*8];     // per (row, ktile): (max, sumexp)
__device__ float2 g_stat2[(size_t)ROWS];      // per row: (max, 1/l)
__device__ float  g_O[(size_t)MROW*DMODEL];   // (O1+O2) in [B,L,D] layout

// ---------------- tf32 mma helpers -----------------------------------------
__device__ __forceinline__ unsigned f2tf(float f) {
    unsigned u;
    asm("cvt.rna.tf32.f32 %0, %1;" : "=r"(u) : "f"(f));
    return u;
}

__device__ __forceinline__ void mma_tf32(float* d, const unsigned* a, const unsigned* b) {
    asm volatile(
        "mma.sync.aligned.m16n8k8.row.col.f32.tf32.tf32.f32 "
        "{%0,%1,%2,%3}, {%4,%5,%6,%7}, {%8,%9}, {%0,%1,%2,%3};\n"
        : "+f"(d[0]), "+f"(d[1]), "+f"(d[2]), "+f"(d[3])
        : "r"(a[0]), "r"(a[1]), "r"(a[2]), "r"(a[3]), "r"(b[0]), "r"(b[1]));
}

__device__ __forceinline__ void ldsm_x4(unsigned* r, uint32_t addr) {
    asm volatile("ldmatrix.sync.aligned.m8n8.x4.shared.b16 {%0,%1,%2,%3}, [%4];"
        : "=r"(r[0]), "=r"(r[1]), "=r"(r[2]), "=r"(r[3]) : "r"(addr));
}

// ======= big GEMM core (R10-proven: single buffer, prefetch, ldmatrix) ======
template<bool HEADMAJOR>
__device__ __forceinline__ void gemm_core(
    const float* __restrict__ A, const float* __restrict__ W,
    const float* __restrict__ bias, float* __restrict__ C)
{
    const int K = DMODEL, N = DMODEL;
    __shared__ __align__(16) unsigned As[128][36];
    __shared__ __align__(16) unsigned Bs[32][136];
    int tid = threadIdx.x;
    int bm = blockIdx.y * 128, bn = blockIdx.x * 128;
    int warp = tid >> 5, lane = tid & 31;
    int wm = (warp >> 2) * 64, wn = (warp & 3) * 32;
    int g = lane >> 2, i4 = lane & 3;

    int lrow = (lane & 7) + 8 * ((lane >> 3) & 1);
    int lcol = 4 * (lane >> 4);
    uint32_t a_base = (uint32_t)__cvta_generic_to_shared(&As[0][0]);

    float acc[4][4][4] = {};
    int am = tid >> 3, ak = (tid & 7) * 4;
    int bk2 = tid >> 5, bn4 = (tid & 31) * 4;

    float4 ra[4], rw[4];
#pragma unroll
    for (int r = 0; r < 4; r++) {
        ra[r] = *(const float4*)&A[(size_t)(bm + am + 32 * r) * K + ak];
        rw[r] = *(const float4*)&W[(size_t)(bk2 + 8 * r) * N + bn + bn4];
    }

    for (int k0 = 0; k0 < K; k0 += 32) {
#pragma unroll
        for (int r = 0; r < 4; r++) {
            *(uint4*)&As[am + 32 * r][ak] =
                make_uint4(f2tf(ra[r].x), f2tf(ra[r].y), f2tf(ra[r].z), f2tf(ra[r].w));
            *(uint4*)&Bs[bk2 + 8 * r][bn4] =
                make_uint4(f2tf(rw[r].x), f2tf(rw[r].y), f2tf(rw[r].z), f2tf(rw[r].w));
        }
        __syncthreads();
        if (k0 + 32 < K) {
#pragma unroll
            for (int r = 0; r < 4; r++) {
                ra[r] = *(const float4*)&A[(size_t)(bm + am + 32 * r) * K + k0 + 32 + ak];
                rw[r] = *(const float4*)&W[(size_t)(k0 + 32 + bk2 + 8 * r) * N + bn + bn4];
            }
        }
#pragma unroll
        for (int ks = 0; ks < 32; ks += 8) {
            unsigned af[4][4], bf[4][2];
#pragma unroll
            for (int mi = 0; mi < 4; mi++)
                ldsm_x4(af[mi],
                    a_base + ((wm + 16 * mi + lrow) * 36 + ks + lcol) * 4);
#pragma unroll
            for (int ni = 0; ni < 4; ni++) {
                bf[ni][0] = Bs[ks + i4][wn + 8 * ni + g];
                bf[ni][1] = Bs[ks + i4 + 4][wn + 8 * ni + g];
            }
#pragma unroll
            for (int mi = 0; mi < 4; mi++)
#pragma unroll
                for (int ni = 0; ni < 4; ni++)
                    mma_tf32(acc[mi][ni], af[mi], bf[ni]);
        }
        __syncthreads();
    }

#pragma unroll
    for (int mi = 0; mi < 4; mi++) {
#pragma unroll
        for (int ni = 0; ni < 4; ni++) {
#pragma unroll
            for (int e = 0; e < 4; e++) {
                int r = bm + wm + 16 * mi + g + (e >> 1) * 8;
                int c = bn + wn + 8 * ni + 2 * i4 + (e & 1);
                float v = acc[mi][ni][e] + bias[c];
                if (HEADMAJOR) {
                    int b = r >> 10, l = r & 1023, h = c >> 6, dd = c & 63;
                    C[(((size_t)(b * NH + h) * LSEQ + l) << 6) + dd] = v;
                } else {
                    C[(size_t)r * DMODEL + c] = v;
                }
            }
        }
    }
}

// ========== merged QKV projection (z selects Q/K/V), head-major =============
__global__ void __launch_bounds__(256) gemm_qkv(
    const float* __restrict__ A,
    const float* __restrict__ Wq, const float* __restrict__ bq,
    const float* __restrict__ Wk, const float* __restrict__ bk,
    const float* __restrict__ Wv, const float* __restrict__ bv)
{
    int zz = blockIdx.z;
    const float* W    = (zz == 0) ? Wq : (zz == 1) ? Wk : Wv;
    const float* bias = (zz == 0) ? bq : (zz == 1) ? bk : bv;
    float* C          = (zz == 0) ? g_Q : (zz == 1) ? g_K : g_V;
    gemm_core<true>(A, W, bias, C);
}

// ============ out projection: out = g_O @ Wo + bo (row-major) ===============
__global__ void __launch_bounds__(256) gemm_out(
    const float* __restrict__ W, const float* __restrict__ bias,
    float* __restrict__ C)
{
    gemm_core<false>(g_O, W, bias, C);
}

// ======== R = Q @ posK^T (tf32 mma; M=65536, N=257->3x128, K=64) ===========
__global__ void __launch_bounds__(256) gemm_qposk_t(const float* __restrict__ posK)
{
    __shared__ __align__(16) unsigned As[128][36];
    __shared__ __align__(16) unsigned Bs[32][132];
    int tid = threadIdx.x;
    int bm = blockIdx.y * 128, bn = blockIdx.x * 128;
    int warp = tid >> 5, lane = tid & 31;
    int wm = (warp >> 2) * 64, wn = (warp & 3) * 32;
    int g = lane >> 2, i4 = lane & 3;

    int lrow = (lane & 7) + 8 * ((lane >> 3) & 1);
    int lcol = 4 * (lane >> 4);
    uint32_t a_base = (uint32_t)__cvta_generic_to_shared(&As[0][0]);

    float acc[4][4][4] = {};
    int am = tid >> 3, ak = (tid & 7) * 4;
    int nl = tid >> 3, k4 = (tid & 7) * 4;

    for (int k0 = 0; k0 < DH; k0 += 32) {
#pragma unroll
        for (int r = 0; r < 4; r++) {
            float4 v = *(const float4*)&g_Q[(size_t)(bm + am + 32 * r) * DH + k0 + ak];
            *(uint4*)&As[am + 32 * r][ak] =
                make_uint4(f2tf(v.x), f2tf(v.y), f2tf(v.z), f2tf(v.w));
            int n = bn + nl + 32 * r;
            float4 w = make_float4(0.f, 0.f, 0.f, 0.f);
            if (n < NPOS) w = *(const float4*)&posK[(size_t)n * DH + k0 + k4];
            Bs[k4 + 0][nl + 32 * r] = f2tf(w.x);
            Bs[k4 + 1][nl + 32 * r] = f2tf(w.y);
            Bs[k4 + 2][nl + 32 * r] = f2tf(w.z);
            Bs[k4 + 3][nl + 32 * r] = f2tf(w.w);
        }
        __syncthreads();
#pragma unroll
        for (int ks = 0; ks < 32; ks += 8) {
            unsigned af[4][4], bf[4][2];
#pragma unroll
            for (int mi = 0; mi < 4; mi++)
                ldsm_x4(af[mi],
                    a_base + ((wm + 16 * mi + lrow) * 36 + ks + lcol) * 4);
#pragma unroll
            for (int ni = 0; ni < 4; ni++) {
                bf[ni][0] = Bs[ks + i4][wn + 8 * ni + g];
                bf[ni][1] = Bs[ks + i4 + 4][wn + 8 * ni + g];
            }
#pragma unroll
            for (int mi = 0; mi < 4; mi++)
#pragma unroll
                for (int ni = 0; ni < 4; ni++)
                    mma_tf32(acc[mi][ni], af[mi], bf[ni]);
        }
        __syncthreads();
    }

#pragma unroll
    for (int mi = 0; mi < 4; mi++) {
#pragma unroll
        for (int ni = 0; ni < 4; ni++) {
#pragma unroll
            for (int e = 0; e < 4; e++) {
                int r = bm + wm + 16 * mi + g + (e >> 1) * 8;
                int n = bn + wn + 8 * ni + 2 * i4 + (e & 1);
                if (n < NPOS) g_R[(size_t)r * NPOS + n] = acc[mi][ni][e];
            }
        }
    }
}

// ===== S = (Q K^T + gather(R)) * 0.125 * pad  +  per-tile softmax stats =====
// Off-diag tiles: one r2 per row. float2 stores. Shuffle-reduced stats.
__global__ void __launch_bounds__(256) attn_scores_t(const float* __restrict__ pad)
{
    __shared__ __align__(16) unsigned Qs[128][36];
    __shared__ __align__(16) unsigned Ks[128][36];
    int z = blockIdx.z;
    const float* Qp = g_Q + (size_t)z * LSEQ * DH;
    const float* Kp = g_K + (size_t)z * LSEQ * DH;
    int bm = blockIdx.y * 128, bn = blockIdx.x * 128;
    int tid = threadIdx.x;
    int warp = tid >> 5, lane = tid & 31;
    int wm = (warp >> 2) * 64, wn = (warp & 3) * 32;
    int g = lane >> 2, i4 = lane & 3;

    int lrow = (lane & 7) + 8 * ((lane >> 3) & 1);
    int lcol = 4 * (lane >> 4);
    int brow = (lane & 7) + 8 * (lane >> 4);
    int bcol = 4 * ((lane >> 3) & 1);
    uint32_t q_base = (uint32_t)__cvta_generic_to_shared(&Qs[0][0]);
    uint32_t k_base = (uint32_t)__cvta_generic_to_shared(&Ks[0][0]);

    float acc[4][4][4] = {};
    int am = tid >> 3, ak = (tid & 7) * 4;

    for (int k0 = 0; k0 < DH; k0 += 32) {
#pragma unroll
        for (int r = 0; r < 4; r++) {
            float4 v = *(const float4*)&Qp[(size_t)(bm + am + 32 * r) * DH + k0 + ak];
            *(uint4*)&Qs[am + 32 * r][ak] =
                make_uint4(f2tf(v.x), f2tf(v.y), f2tf(v.z), f2tf(v.w));
            float4 w = *(const float4*)&Kp[(size_t)(bn + am + 32 * r) * DH + k0 + ak];
            *(uint4*)&Ks[am + 32 * r][ak] =
                make_uint4(f2tf(w.x), f2tf(w.y), f2tf(w.z), f2tf(w.w));
        }
        __syncthreads();
#pragma unroll
        for (int ks = 0; ks < 32; ks += 8) {
            unsigned af[4][4], bfr[2][4];
#pragma unroll
            for (int mi = 0; mi < 4; mi++)
                ldsm_x4(af[mi],
                    q_base + ((wm + 16 * mi + lrow) * 36 + ks + lcol) * 4);
#pragma unroll
            for (int p = 0; p < 2; p++)
                ldsm_x4(bfr[p],
                    k_base + ((wn + 16 * p + brow) * 36 + ks + bcol) * 4);
#pragma unroll
            for (int mi = 0; mi < 4; mi++)
#pragma unroll
                for (int ni = 0; ni < 4; ni++)
                    mma_tf32(acc[mi][ni], af[mi], &bfr[ni >> 1][(ni & 1) * 2]);
        }
        __syncthreads();
    }

    int b = z >> 4;
    int warp4 = warp & 3;
    float* smax = (float*)&Qs[0][0];   // 128*4
    float* ssum = smax + 512;          // 128*4
    float* rowm = ssum + 512;          // 128
    float* padS = (float*)&Ks[0][0];   // 128
    float* rowr = padS + 128;          // 128

    bool diag = (bn - bm < 256) && (bm - bn < 256);
    if (tid < 128) {
        padS[tid] = pad[b * LSEQ + bn + tid];
        if (!diag) {
            int q = bm + tid;
            rowr[tid] = g_R[((size_t)z * LSEQ + q) * NPOS + ((bn > bm) ? 256 : 0)];
        }
    }
    __syncthreads();

    // pass 1: paired score computation + float2 store; shuffle-reduced max
#pragma unroll
    for (int mi = 0; mi < 4; mi++) {
#pragma unroll
        for (int e1 = 0; e1 < 2; e1++) {
            int rl = wm + 16 * mi + g + 8 * e1;
            int q = bm + rl;
            float mx = -3.0e38f;
            float r2c = diag ? 0.f : rowr[rl];
            const float* Rrow = &g_R[((size_t)z * LSEQ + q) * NPOS + 128];
            float* Srow = &g_S[((size_t)z * LSEQ + q) * LSEQ];
#pragma unroll
            for (int ni = 0; ni < 4; ni++) {
                int kp0 = bn + wn + 8 * ni + 2 * i4;
                float r20 = r2c, r21 = r2c;
                if (diag) {
                    int d0 = min(max(kp0 - q, -128), 128);
                    int d1 = min(max(kp0 + 1 - q, -128), 128);
                    r20 = Rrow[d0];
                    r21 = Rrow[d1];
                }
                float2 pd = *(float2*)&padS[kp0 - bn];
                float s0 = (acc[mi][ni][e1 * 2]     + r20) * 0.125f * pd.x;
                float s1 = (acc[mi][ni][e1 * 2 + 1] + r21) * 0.125f * pd.y;
                *(float2*)&Srow[kp0] = make_float2(s0, s1);
                acc[mi][ni][e1 * 2]     = s0;
                acc[mi][ni][e1 * 2 + 1] = s1;
                mx = fmaxf(mx, fmaxf(s0, s1));
            }
            mx = fmaxf(mx, __shfl_xor_sync(0xffffffffu, mx, 1));
            mx = fmaxf(mx, __shfl_xor_sync(0xffffffffu, mx, 2));
            if (i4 == 0) smax[rl * 4 + warp4] = mx;
        }
    }
    __syncthreads();
    if (tid < 128) {
        float m = smax[tid * 4];
#pragma unroll
        for (int j = 1; j < 4; j++) m = fmaxf(m, smax[tid * 4 + j]);
        rowm[tid] = m;
    }
    __syncthreads();
#pragma unroll
    for (int mi = 0; mi < 4; mi++) {
#pragma unroll
        for (int e1 = 0; e1 < 2; e1++) {
            int rl = wm + 16 * mi + g + 8 * e1;
            float m = rowm[rl];
            float se = 0.f;
#pragma unroll
            for (int ni = 0; ni < 4; ni++)
#pragma unroll
                for (int e0 = 0; e0 < 2; e0++)
                    se += __expf(acc[mi][ni][e1 * 2 + e0] - m);
            se += __shfl_xor_sync(0xffffffffu, se, 1);
            se += __shfl_xor_sync(0xffffffffu, se, 2);
            if (i4 == 0) ssum[rl * 4 + warp4] = se;
        }
    }
    __syncthreads();
    if (tid < 128) {
        float l = 0.f;
#pragma unroll
        for (int j = 0; j < 4; j++) l += ssum[tid * 4 + j];
        int q = bm + tid;
        g_stat[((size_t)z * LSEQ + q) * 8 + blockIdx.x] = make_float2(rowm[tid], l);
    }
}

// ====== combine per-tile stats -> per-row (max, 1/l) ========================
__global__ void __launch_bounds__(256) combine_stats()
{
    int row = blockIdx.x * 256 + threadIdx.x;
    const float2* st = &g_stat[(size_t)row * 8];
    float m = st[0].x;
#pragma unroll
    for (int j = 1; j < 8; j++) m = fmaxf(m, st[j].x);
    float l = 0.f;
#pragma unroll
    for (int j = 0; j < 8; j++) l += st[j].y * __expf(st[j].x - m);
    g_stat2[row] = make_float2(m, 1.f / l);
}

// ====== zero g_T (uncovered bins + padding must be 0 before av scatter) =====
__global__ void __launch_bounds__(256) zero_T()
{
    size_t i = ((size_t)blockIdx.x * 256 + threadIdx.x) * 4;
    *(float4*)&g_T[i] = make_float4(0.f, 0.f, 0.f, 0.f);
}

// ====== O1 = P @ V fused with T scatter (P on the fly from raw S) ===========
__global__ void __launch_bounds__(256) gemm_av_t()
{
    __shared__ __align__(16) unsigned As[128][36];
    __shared__ __align__(16) unsigned Bs[32][72];
    __shared__ float rs[256];
    int z = blockIdx.y;
    const float* S = g_S + (size_t)z * LSEQ * LSEQ;
    const float* V = g_V + (size_t)z * LSEQ * DH;
    int bm = blockIdx.x * 128;
    int tid = threadIdx.x;
    int warp = tid >> 5, lane = tid & 31;
    int wm = (warp >> 1) * 32, wn = (warp & 1) * 32;
    int g = lane >> 2, i4 = lane & 3;

    int lrow = (lane & 7) + 8 * ((lane >> 3) & 1);
    int lcol = 4 * (lane >> 4);
    uint32_t a_base = (uint32_t)__cvta_generic_to_shared(&As[0][0]);

    if (tid < 128) {
        float2 st = g_stat2[(size_t)z * LSEQ + bm + tid];
        rs[tid * 2] = st.x;
        rs[tid * 2 + 1] = st.y;
    }
    __syncthreads();

    float acc[2][4][4] = {};
    int am = tid >> 3, ak = (tid & 7) * 4;
    int vk = tid >> 4, vn4 = (tid & 15) * 4;
    float te0[4] = {}, te1[4] = {};

    float4 ra[4], rv[2];
#pragma unroll
    for (int r = 0; r < 4; r++)
        ra[r] = *(const float4*)&S[(size_t)(bm + am + 32 * r) * LSEQ + ak];
#pragma unroll
    for (int r = 0; r < 2; r++)
        rv[r] = *(const float4*)&V[(size_t)(vk + 16 * r) * DH + vn4];

    for (int k0 = 0; k0 < LSEQ; k0 += 32) {
#pragma unroll
        for (int r = 0; r < 4; r++) {
            int rl = am + 32 * r;
            float m = rs[2 * rl], il = rs[2 * rl + 1];
            float p0 = __expf(ra[r].x - m) * il;
            float p1 = __expf(ra[r].y - m) * il;
            float p2 = __expf(ra[r].z - m) * il;
            float p3 = __expf(ra[r].w - m) * il;
            *(uint4*)&As[rl][ak] = make_uint4(f2tf(p0), f2tf(p1), f2tf(p2), f2tf(p3));
            float* Trow = g_T + (size_t)((size_t)z * LSEQ + bm + rl) * TP;
            int binb = k0 + ak - bm - rl + 128;
            if (binb >= 1 && binb <= 252) {    // whole group in middle bins
                Trow[binb]     = p0;
                Trow[binb + 1] = p1;
                Trow[binb + 2] = p2;
                Trow[binb + 3] = p3;
            } else {
                if (binb     <= 0) te0[r] += p0; else if (binb     >= 256) te1[r] += p0; else Trow[binb]     = p0;
                if (binb + 1 <= 0) te0[r] += p1; else if (binb + 1 >= 256) te1[r] += p1; else Trow[binb + 1] = p1;
                if (binb + 2 <= 0) te0[r] += p2; else if (binb + 2 >= 256) te1[r] += p2; else Trow[binb + 2] = p2;
                if (binb + 3 <= 0) te0[r] += p3; else if (binb + 3 >= 256) te1[r] += p3; else Trow[binb + 3] = p3;
            }
        }
#pragma unroll
        for (int r = 0; r < 2; r++)
            *(uint4*)&Bs[vk + 16 * r][vn4] =
                make_uint4(f2tf(rv[r].x), f2tf(rv[r].y), f2tf(rv[r].z), f2tf(rv[r].w));
        __syncthreads();
        if (k0 + 32 < LSEQ) {
#pragma unroll
            for (int r = 0; r < 4; r++)
                ra[r] = *(const float4*)&S[(size_t)(bm + am + 32 * r) * LSEQ + k0 + 32 + ak];
#pragma unroll
            for (int r = 0; r < 2; r++)
                rv[r] = *(const float4*)&V[(size_t)(k0 + 32 + vk + 16 * r) * DH + vn4];
        }
#pragma unroll
        for (int ks = 0; ks < 32; ks += 8) {
            unsigned af[2][4], bf[4][2];
#pragma unroll
            for (int mi = 0; mi < 2; mi++)
                ldsm_x4(af[mi],
                    a_base + ((wm + 16 * mi + lrow) * 36 + ks + lcol) * 4);
#pragma unroll
            for (int ni = 0; ni < 4; ni++) {
                bf[ni][0] = Bs[ks + i4][wn + 8 * ni + g];
                bf[ni][1] = Bs[ks + i4 + 4][wn + 8 * ni + g];
            }
#pragma unroll
            for (int mi = 0; mi < 2; mi++)
#pragma unroll
                for (int ni = 0; ni < 4; ni++)
                    mma_tf32(acc[mi][ni], af[mi], bf[ni]);
        }
        __syncthreads();
    }

    {
        float* e0s = (float*)&As[0][0];
        float* e1s = e0s + 1024;
#pragma unroll
        for (int r = 0; r < 4; r++) {
            e0s[(am + 32 * r) * 8 + (tid & 7)] = te0[r];
            e1s[(am + 32 * r) * 8 + (tid & 7)] = te1[r];
        }
        __syncthreads();
        if (tid < 128) {
            float a0 = 0.f, a1 = 0.f;
#pragma unroll
            for (int j = 0; j < 8; j++) { a0 += e0s[tid * 8 + j]; a1 += e1s[tid * 8 + j]; }
            float* Trow = g_T + (size_t)((size_t)z * LSEQ + bm + tid) * TP;
            Trow[0] = a0;
            Trow[256] = a1;
        }
    }

    int b = z >> 4, h = z & 15;
#pragma unroll
    for (int mi = 0; mi < 2; mi++) {
#pragma unroll
        for (int ni = 0; ni < 4; ni++) {
#pragma unroll
            for (int e = 0; e < 4; e++) {
                int q = bm + wm + 16 * mi + g + (e >> 1) * 8;
                int n = wn + 8 * ni + 2 * i4 + (e & 1);
                g_O[((size_t)(b * LSEQ + q)) * DMODEL + h * 64 + n] = acc[mi][ni][e];
            }
        }
    }
}

// ====== g_O += T @ posV (tf32 mma; M=65536, N=64, K=288 padded) ============
__global__ void __launch_bounds__(256) gemm_tposv_t(const float* __restrict__ posV)
{
    __shared__ __align__(16) unsigned As[128][36];
    __shared__ __align__(16) unsigned Bs[32][72];
    int bm = blockIdx.x * 128;
    int tid = threadIdx.x;
    int warp = tid >> 5, lane = tid & 31;
    int wm = warp * 16;
    int g = lane >> 2, i4 = lane & 3;

    int lrow = (lane & 7) + 8 * ((lane >> 3) & 1);
    int lcol = 4 * (lane >> 4);
    uint32_t a_base = (uint32_t)__cvta_generic_to_shared(&As[0][0]);

    float acc[8][4] = {};
    int am = tid >> 3, ak = (tid & 7) * 4;
    int vk = tid >> 4, vn4 = (tid & 15) * 4;

    for (int k0 = 0; k0 < TP; k0 += 32) {
#pragma unroll
        for (int r = 0; r < 4; r++) {
            float4 v = *(const float4*)&g_T[(size_t)(bm + am + 32 * r) * TP + k0 + ak];
            *(uint4*)&As[am + 32 * r][ak] =
                make_uint4(f2tf(v.x), f2tf(v.y), f2tf(v.z), f2tf(v.w));
        }
#pragma unroll
        for (int r = 0; r < 2; r++) {
            int k = k0 + vk + 16 * r;
            float4 w = make_float4(0.f, 0.f, 0.f, 0.f);
            if (k < NPOS) w = *(const float4*)&posV[(size_t)k * DH + vn4];
            *(uint4*)&Bs[vk + 16 * r][vn4] =
                make_uint4(f2tf(w.x), f2tf(w.y), f2tf(w.z), f2tf(w.w));
        }
        __syncthreads();
#pragma unroll
        for (int ks = 0; ks < 32; ks += 8) {
            unsigned af[4], bf[8][2];
            ldsm_x4(af, a_base + ((wm + lrow) * 36 + ks + lcol) * 4);
#pragma unroll
            for (int ni = 0; ni < 8; ni++) {
                bf[ni][0] = Bs[ks + i4][8 * ni + g];
                bf[ni][1] = Bs[ks + i4 + 4][8 * ni + g];
            }
#pragma unroll
            for (int ni = 0; ni < 8; ni++)
                mma_tf32(acc[ni], af, bf[ni]);
        }
        __syncthreads();
    }

#pragma unroll
    for (int ni = 0; ni < 8; ni++) {
#pragma unroll
        for (int e = 0; e < 4; e++) {
            int r = bm + wm + g + (e >> 1) * 8;
            int z = r >> 10, q = r & 1023;
            int b = z >> 4, h = z & 15;
            int n = 8 * ni + 2 * i4 + (e & 1);
            size_t idx = ((size_t)(b * LSEQ + q)) * DMODEL + h * 64 + n;
            g_O[idx] += acc[ni][e];
        }
    }
}

// ---------------------------------------------------------------------------
extern "C" void kernel_launch(void* const* d_in, const int* in_sizes, int n_in,
                              void* d_out, int out_size)
{
    const float* x    = (const float*)d_in[0];
    const float* pad  = (const float*)d_in[1];
    const float* Wq   = (const float*)d_in[2];
    const float* bq   = (const float*)d_in[3];
    const float* Wk   = (const float*)d_in[4];
    const float* bk   = (const float*)d_in[5];
    const float* Wv   = (const float*)d_in[6];
    const float* bv   = (const float*)d_in[7];
    const float* Wo   = (const float*)d_in[8];
    const float* bo   = (const float*)d_in[9];
    const float* posK = (const float*)d_in[10];
    const float* posV = (const float*)d_in[11];
    float* out = (float*)d_out;

    gemm_qkv<<<dim3(DMODEL / 128, MROW / 128, 3), 256>>>(x, Wq, bq, Wk, bk, Wv, bv);
    gemm_qposk_t<<<dim3(3, ROWS / 128), 256>>>(posK);
    zero_T<<<(ROWS * TP) / 1024, 256>>>();
    attn_scores_t<<<dim3(8, 8, BH), 256>>>(pad);
    combine_stats<<<ROWS / 256, 256>>>();
    gemm_av_t<<<dim3(8, BH), 256>>>();
    gemm_tposv_t<<<dim3(ROWS / 128), 256>>>(posV);
    gemm_out<<<dim3(DMODEL / 128, MROW / 128), 256>>>(Wo, bo, out);
}